// round 3
// baseline (speedup 1.0000x reference)
#include <cuda_runtime.h>
#include <cuda_fp16.h>
#include <cstdint>

// ============================================================================
// QuantLinear: out[M,N] = x[M,K] @ dequant(qweight, scales, qzeros)[K,N]
// M=8192, K=4096, N=11008, groupsize=128, 4-bit.
//
// compute_103 PTX target => no tcgen05; tensor path = mma.sync HMMA.
//
// Pass 1: x fp32 -> g_X fp16 [M,K]
// Pass 2: fused GEMM: CTA 128x256x64, 3 stages, 8 warps (2x4), warp 64x64.
//         A via cp.async (fp16), B dequanted in-register from qweight (L2-
//         resident 4-bit) and STS'd to smem -> B-side LTS traffic / 4.
// ============================================================================

constexpr int M = 8192;
constexpr int N = 11008;
constexpr int K = 4096;

constexpr int BM = 128;
constexpr int BN = 256;
constexpr int KC = 64;             // halves per stage = 128B rows (SW128)
constexpr int STAGES = 3;
constexpr int NK = K / KC;         // 64
constexpr int THREADS = 256;

constexpr int A_BYTES = BM * 128;                   // 16384
constexpr int B_BYTES = BN * 128;                   // 32768
constexpr int STAGE_BYTES = A_BYTES + B_BYTES;      // 49152
constexpr int SMEM_BYTES = STAGES * STAGE_BYTES;    // 147456

static_assert(M % BM == 0 && N % BN == 0 && K % KC == 0, "exact tiling");

__device__ __half g_X[(size_t)M * K];   // [M, K] fp16

// ----------------------------------------------------------------------------
// helpers
// ----------------------------------------------------------------------------
__device__ __forceinline__ void cp16(uint32_t smem_dst, const void* gsrc) {
    asm volatile("cp.async.cg.shared.global [%0], [%1], 16;"
                 :: "r"(smem_dst), "l"(gsrc));
}

__device__ __forceinline__ void ldsm4(uint32_t* r, uint32_t addr) {
    asm volatile("ldmatrix.sync.aligned.m8n8.x4.shared.b16 {%0,%1,%2,%3}, [%4];"
                 : "=r"(r[0]), "=r"(r[1]), "=r"(r[2]), "=r"(r[3]) : "r"(addr));
}

__device__ __forceinline__ void mma16816(float* c, const uint32_t* a, const uint32_t* b) {
    asm volatile(
        "mma.sync.aligned.m16n8k16.row.col.f32.f16.f16.f32 "
        "{%0,%1,%2,%3}, {%4,%5,%6,%7}, {%8,%9}, {%0,%1,%2,%3};"
        : "+f"(c[0]), "+f"(c[1]), "+f"(c[2]), "+f"(c[3])
        : "r"(a[0]), "r"(a[1]), "r"(a[2]), "r"(a[3]), "r"(b[0]), "r"(b[1]));
}

// Dequant one qweight word (8 k-nibbles at one n) -> 8 halves, STS 16B.
__device__ __forceinline__ void sts_dequant(uint32_t dst, uint32_t w,
                                            float s, float sz) {
    __half2 h[4];
#pragma unroll
    for (int j = 0; j < 4; j++) {
        float v0 = fmaf(s, (float)((w >> (8 * j))     & 0xF), -sz);
        float v1 = fmaf(s, (float)((w >> (8 * j + 4)) & 0xF), -sz);
        h[j] = __floats2half2_rn(v0, v1);
    }
    uint4 u = *(uint4*)h;
    asm volatile("st.shared.v4.b32 [%0], {%1,%2,%3,%4};"
                 :: "r"(dst), "r"(u.x), "r"(u.y), "r"(u.z), "r"(u.w) : "memory");
}

// ----------------------------------------------------------------------------
// Pass 1: x fp32 -> fp16
// ----------------------------------------------------------------------------
__global__ void __launch_bounds__(256)
convert_x_kernel(const float* __restrict__ x) {
    int idx = blockIdx.x * 256 + threadIdx.x;      // over M*K/4 (exact)
    float4 v = ((const float4*)x)[idx];
    __half2 h0 = __floats2half2_rn(v.x, v.y);
    __half2 h1 = __floats2half2_rn(v.z, v.w);
    uint2 o;
    o.x = *(unsigned*)&h0;
    o.y = *(unsigned*)&h1;
    ((uint2*)g_X)[idx] = o;
}

// ----------------------------------------------------------------------------
// Pass 2: fused dequant + GEMM
// Per-thread B mapping (it = 0..7): idx = tid + it*256, row n = idx>>3 (0..255),
// chunk c = idx&7. word = qweight[(kt*8 + c)*N + n0 + n]. SW128 swizzled STS.
// ----------------------------------------------------------------------------
__global__ void __launch_bounds__(THREADS)
gemm_kernel(const int* __restrict__ qweight, const float* __restrict__ scales,
            const int* __restrict__ qzeros, float* __restrict__ out) {
    extern __shared__ char smem[];
    const uint32_t sbase = (uint32_t)__cvta_generic_to_shared(smem);
    const int tid  = threadIdx.x;
    const int warp = tid >> 5;
    const int lane = tid & 31;
    const int wm = warp & 1;          // 2 warps over 128 M
    const int wn = warp >> 1;         // 4 warps over 256 N (64 each)
    const int m0 = blockIdx.x * BM;
    const int n0 = blockIdx.y * BN;

    const __half* Ag = g_X + (size_t)m0 * K;
    const unsigned* Qg = (const unsigned*)qweight;

    // B-load thread geometry
    const int rbase = tid >> 3;           // n row for it=0 (rows rbase + 32*it)
    const int cq    = tid & 7;            // k-chunk (qweight row offset)

    float acc[4][8][4];
#pragma unroll
    for (int i = 0; i < 4; i++)
#pragma unroll
        for (int j = 0; j < 8; j++)
#pragma unroll
            for (int e = 0; e < 4; e++) acc[i][j][e] = 0.f;

    // per-thread scale / scale*zero for the 8 rows it serves, for current group
    float sreg[8], szreg[8];
    int gcur = -1;
    auto reload_sz = [&](int g) {
#pragma unroll
        for (int it = 0; it < 8; it++) {
            int r = rbase + 32 * it;
            float s = scales[(size_t)g * N + n0 + r];
            unsigned qz = ((const unsigned*)qzeros)[(size_t)g * (N / 8) + (n0 >> 3) + (r >> 3)];
            float z = (float)((qz >> ((r & 7) * 4)) & 0xF);
            sreg[it] = s;
            szreg[it] = s * z;
        }
        gcur = g;
    };

    uint32_t breg[2][8];
    auto ldg_b = [&](int kt, int buf) {
#pragma unroll
        for (int it = 0; it < 8; it++) {
            int r = rbase + 32 * it;
            breg[buf][it] = Qg[(size_t)(kt * 8 + cq) * N + n0 + r];
        }
    };
    auto sts_b = [&](int kt, int buf) {
        int g = kt >> 1;
        if (g != gcur) reload_sz(g);
        const uint32_t b_s = sbase + (kt % STAGES) * STAGE_BYTES + A_BYTES;
#pragma unroll
        for (int it = 0; it < 8; it++) {
            int r = rbase + 32 * it;
            uint32_t off = (uint32_t)r * 128 + (uint32_t)((cq ^ (r & 7)) * 16);
            sts_dequant(b_s + off, breg[buf][it], sreg[it], szreg[it]);
        }
    };
    auto cpa_a = [&](int kt) {
        const uint32_t a_s = sbase + (kt % STAGES) * STAGE_BYTES;
        const __half* Ak = Ag + kt * KC;
#pragma unroll
        for (int it = 0; it < 4; it++) {       // 128 rows * 8 chunks / 256 thr
            int idx = tid + it * THREADS;
            int r = idx >> 3, c = idx & 7;
            uint32_t off = (uint32_t)r * 128 + (uint32_t)((c ^ (r & 7)) * 16);
            cp16(a_s + off, Ak + (size_t)r * K + c * 8);
        }
    };

    // ldmatrix address components
    const int arow = wm * 64 + (lane & 15);
    const int asel = lane >> 4;
    const int brow = wn * 64 + (((lane >> 4) & 1) << 3) + (lane & 7);
    const int bsel = (lane >> 3) & 1;

    // prologue: tiles 0,1 in flight; stage 0 fully resident after sync
    ldg_b(0, 0);
    cpa_a(0);
    asm volatile("cp.async.commit_group;" ::: "memory");
    ldg_b(1, 1);
    cpa_a(1);
    asm volatile("cp.async.commit_group;" ::: "memory");
    sts_b(0, 0);
    asm volatile("cp.async.wait_group 1;" ::: "memory");
    __syncthreads();

    for (int i = 0; i < NK; i++) {
        // stage i resident. Prepare stage i+1 (STS B) and i+2 (LDG B + cp.async A).
        if (i + 1 < NK) sts_b(i + 1, (i + 1) & 1);
        if (i + 2 < NK) {
            ldg_b(i + 2, i & 1);
            cpa_a(i + 2);
        }
        asm volatile("cp.async.commit_group;" ::: "memory");

        const uint32_t a_s = sbase + (i % STAGES) * STAGE_BYTES;
        const uint32_t b_s = a_s + A_BYTES;
#pragma unroll
        for (int ks = 0; ks < KC / 16; ks++) {
            uint32_t a[4][4], b[4][4];
#pragma unroll
            for (int mf = 0; mf < 4; mf++) {
                int row = arow + mf * 16;
                int kc  = ks * 2 + asel;
                ldsm4(a[mf], a_s + row * 128 + ((kc ^ (row & 7)) * 16));
            }
#pragma unroll
            for (int nf2 = 0; nf2 < 4; nf2++) {
                int row = brow + nf2 * 16;
                int kc  = ks * 2 + bsel;
                ldsm4(b[nf2], b_s + row * 128 + ((kc ^ (row & 7)) * 16));
            }
#pragma unroll
            for (int mf = 0; mf < 4; mf++)
#pragma unroll
                for (int nf = 0; nf < 8; nf++)
                    mma16816(acc[mf][nf], a[mf], &b[nf >> 1][(nf & 1) * 2]);
        }

        asm volatile("cp.async.wait_group 1;" ::: "memory");
        __syncthreads();
    }

    // Epilogue: direct register -> gmem (float2 stores)
    const int mbase = m0 + wm * 64 + (lane >> 2);
    const int nbase = n0 + wn * 64 + (lane & 3) * 2;
#pragma unroll
    for (int mf = 0; mf < 4; mf++)
#pragma unroll
        for (int nf = 0; nf < 8; nf++) {
            float* p0 = &out[(size_t)(mbase + mf * 16)     * N + nbase + nf * 8];
            float* p1 = &out[(size_t)(mbase + mf * 16 + 8) * N + nbase + nf * 8];
            *(float2*)p0 = make_float2(acc[mf][nf][0], acc[mf][nf][1]);
            *(float2*)p1 = make_float2(acc[mf][nf][2], acc[mf][nf][3]);
        }
}

// ----------------------------------------------------------------------------
extern "C" void kernel_launch(void* const* d_in, const int* in_sizes, int n_in,
                              void* d_out, int out_size) {
    (void)in_sizes; (void)n_in; (void)out_size;
    const float* x       = (const float*)d_in[0];
    const int*   qweight = (const int*)d_in[1];
    const float* scales  = (const float*)d_in[2];
    const int*   qzeros  = (const int*)d_in[3];
    float* out = (float*)d_out;

    convert_x_kernel<<<(M * K / 4) / 256, 256>>>(x);

    cudaFuncSetAttribute(gemm_kernel, cudaFuncAttributeMaxDynamicSharedMemorySize,
                         SMEM_BYTES);
    dim3 grid(M / BM, N / BN);   // (64, 43)
    gemm_kernel<<<grid, THREADS, SMEM_BYTES>>>(qweight, scales, qzeros, out);
}

// round 4
// speedup vs baseline: 1.8789x; 1.8789x over previous
#include <cuda_runtime.h>
#include <cuda_fp16.h>
#include <cstdint>

// ============================================================================
// QuantLinear: out[M,N] = x[M,K] @ dequant(qweight, scales, qzeros)[K,N]
// M=8192, K=4096, N=11008, groupsize=128, 4-bit.
//
// compute_103 PTX target => no tcgen05; tensor path = mma.sync HMMA.
//
// Pass 1 (single kernel): x fp32 -> g_X fp16 [M,K]  AND  dequant -> g_W fp16
//        [N,K] (W^T, K-major).
// Pass 2: GEMM: CTA 128x256x64, 512 threads (16 warps, warp 64x32), 3-stage
//        cp.async pipeline, SW128-swizzled smem, m16n8k16 f32 HMMA.
// ============================================================================

constexpr int M = 8192;
constexpr int N = 11008;
constexpr int K = 4096;

constexpr int BM = 128;
constexpr int BN = 256;
constexpr int KC = 64;             // halves per stage = 128B rows (SW128)
constexpr int STAGES = 3;
constexpr int NK = K / KC;         // 64
constexpr int THREADS = 512;

constexpr int A_BYTES = BM * 128;                   // 16384
constexpr int B_BYTES = BN * 128;                   // 32768
constexpr int STAGE_BYTES = A_BYTES + B_BYTES;      // 49152
constexpr int SMEM_BYTES = STAGES * STAGE_BYTES;    // 147456 -> 1 CTA/SM

constexpr int XWORK = M * K / 4;        // float4 items in convert part
constexpr int WWORK = (K / 8) * N;      // int32 items in dequant part

static_assert(M % BM == 0 && N % BN == 0 && K % KC == 0, "exact tiling");

__device__ __half g_X[(size_t)M * K];   // [M, K] fp16
__device__ __half g_W[(size_t)N * K];   // [N, K] fp16 (W^T), K-major

// ----------------------------------------------------------------------------
// helpers
// ----------------------------------------------------------------------------
__device__ __forceinline__ void cp16(uint32_t smem_dst, const void* gsrc) {
    asm volatile("cp.async.cg.shared.global [%0], [%1], 16;"
                 :: "r"(smem_dst), "l"(gsrc));
}

__device__ __forceinline__ void ldsm4(uint32_t* r, uint32_t addr) {
    asm volatile("ldmatrix.sync.aligned.m8n8.x4.shared.b16 {%0,%1,%2,%3}, [%4];"
                 : "=r"(r[0]), "=r"(r[1]), "=r"(r[2]), "=r"(r[3]) : "r"(addr));
}

__device__ __forceinline__ void mma16816(float* c, const uint32_t* a, const uint32_t* b) {
    asm volatile(
        "mma.sync.aligned.m16n8k16.row.col.f32.f16.f16.f32 "
        "{%0,%1,%2,%3}, {%4,%5,%6,%7}, {%8,%9}, {%0,%1,%2,%3};"
        : "+f"(c[0]), "+f"(c[1]), "+f"(c[2]), "+f"(c[3])
        : "r"(a[0]), "r"(a[1]), "r"(a[2]), "r"(a[3]), "r"(b[0]), "r"(b[1]));
}

// ----------------------------------------------------------------------------
// Pass 1: fused x-convert + dequant (one launch; both parts pure streaming)
// ----------------------------------------------------------------------------
__global__ void __launch_bounds__(256)
prep_kernel(const float* __restrict__ x, const int* __restrict__ qweight,
            const float* __restrict__ scales, const int* __restrict__ qzeros) {
    int idx = blockIdx.x * 256 + threadIdx.x;
    if (idx < XWORK) {
        float4 v = ((const float4*)x)[idx];
        __half2 h0 = __floats2half2_rn(v.x, v.y);
        __half2 h1 = __floats2half2_rn(v.z, v.w);
        uint2 o;
        o.x = *(unsigned*)&h0;
        o.y = *(unsigned*)&h1;
        ((uint2*)g_X)[idx] = o;
        return;
    }
    int widx = idx - XWORK;          // over (K/8)*N
    if (widx >= WWORK) return;
    int n = widx % N;
    int r = widx / N;
    int g = r >> 4;                  // groupsize 128 = 16 qweight rows
    unsigned q  = ((const unsigned*)qweight)[widx];
    unsigned qz = ((const unsigned*)qzeros)[g * (N / 8) + (n >> 3)];
    float z = (float)((qz >> ((n & 7) * 4)) & 0xF);
    float s = scales[g * N + n];
    __half2 outv[4];
#pragma unroll
    for (int j = 0; j < 4; j++) {
        float v0 = s * ((float)((q >> (8 * j))     & 0xF) - z);
        float v1 = s * ((float)((q >> (8 * j + 4)) & 0xF) - z);
        outv[j] = __floats2half2_rn(v0, v1);
    }
    *(uint4*)&g_W[(size_t)n * K + r * 8] = *(uint4*)outv;
}

// ----------------------------------------------------------------------------
// Stage loader: A tile (128 rows x 128B) + B tile (256 rows x 128B), SW128.
// Row r, 16B chunk c at r*128 + ((c ^ (r&7))*16).
// ----------------------------------------------------------------------------
__device__ __forceinline__ void load_stage(uint32_t sbase, int slot, int kt,
                                           const __half* Ag, const __half* Bg,
                                           int tid) {
    const uint32_t a_s = sbase + slot * STAGE_BYTES;
    const uint32_t b_s = a_s + A_BYTES;
    const __half* Ak = Ag + kt * KC;
    const __half* Bk = Bg + kt * KC;
#pragma unroll
    for (int it = 0; it < 2; it++) {        // 128 rows * 8 chunks / 512 thr
        int idx = tid + it * THREADS;
        int r = idx >> 3, c = idx & 7;
        uint32_t off = (uint32_t)r * 128 + (uint32_t)((c ^ (r & 7)) * 16);
        cp16(a_s + off, Ak + (size_t)r * K + c * 8);
    }
#pragma unroll
    for (int it = 0; it < 4; it++) {        // 256 rows * 8 chunks / 512 thr
        int idx = tid + it * THREADS;
        int r = idx >> 3, c = idx & 7;
        uint32_t off = (uint32_t)r * 128 + (uint32_t)((c ^ (r & 7)) * 16);
        cp16(b_s + off, Bk + (size_t)r * K + c * 8);
    }
}

// ----------------------------------------------------------------------------
// Pass 2: GEMM
// ----------------------------------------------------------------------------
__global__ void __launch_bounds__(THREADS, 1)
gemm_kernel(float* __restrict__ out) {
    extern __shared__ char smem[];
    const uint32_t sbase = (uint32_t)__cvta_generic_to_shared(smem);
    const int tid  = threadIdx.x;
    const int warp = tid >> 5;
    const int lane = tid & 31;
    const int wm = warp & 1;          // 2 warps over 128 M (64 each)
    const int wn = warp >> 1;         // 8 warps over 256 N (32 each)
    const int m0 = blockIdx.x * BM;
    const int n0 = blockIdx.y * BN;

    const __half* Ag = g_X + (size_t)m0 * K;
    const __half* Bg = g_W + (size_t)n0 * K;

    float acc[4][4][4];
#pragma unroll
    for (int i = 0; i < 4; i++)
#pragma unroll
        for (int j = 0; j < 4; j++)
#pragma unroll
            for (int e = 0; e < 4; e++) acc[i][j][e] = 0.f;

    // ldmatrix address components (canonical x4 ordering):
    const int arow = wm * 64 + (lane & 15);
    const int asel = lane >> 4;                              // k-chunk +0/+1
    const int brow = wn * 32 + (((lane >> 4) & 1) << 3) + (lane & 7);
    const int bsel = (lane >> 3) & 1;

    // prologue
    load_stage(sbase, 0, 0, Ag, Bg, tid);
    asm volatile("cp.async.commit_group;" ::: "memory");
    load_stage(sbase, 1, 1, Ag, Bg, tid);
    asm volatile("cp.async.commit_group;" ::: "memory");

    int slot = 0;
    for (int i = 0; i < NK; i++) {
        asm volatile("cp.async.wait_group 1;" ::: "memory");
        __syncthreads();   // stage i visible; prior compute done before reload

        if (i + 2 < NK) {
            int ns = slot - 1; if (ns < 0) ns += STAGES;     // (i+2) % 3
            load_stage(sbase, ns, i + 2, Ag, Bg, tid);
        }
        asm volatile("cp.async.commit_group;" ::: "memory");

        const uint32_t a_s = sbase + slot * STAGE_BYTES;
        const uint32_t b_s = a_s + A_BYTES;
#pragma unroll
        for (int ks = 0; ks < KC / 16; ks++) {
            uint32_t a[4][4], b[2][4];
#pragma unroll
            for (int mf = 0; mf < 4; mf++) {
                int row = arow + mf * 16;
                int kc  = ks * 2 + asel;
                ldsm4(a[mf], a_s + row * 128 + ((kc ^ (row & 7)) * 16));
            }
#pragma unroll
            for (int nf2 = 0; nf2 < 2; nf2++) {
                int row = brow + nf2 * 16;
                int kc  = ks * 2 + bsel;
                ldsm4(b[nf2], b_s + row * 128 + ((kc ^ (row & 7)) * 16));
            }
#pragma unroll
            for (int mf = 0; mf < 4; mf++)
#pragma unroll
                for (int nf = 0; nf < 4; nf++)
                    mma16816(acc[mf][nf], a[mf], &b[nf >> 1][(nf & 1) * 2]);
        }
        slot++; if (slot == STAGES) slot = 0;
    }

    // Epilogue: register -> gmem float2 stores
    const int mbase = m0 + wm * 64 + (lane >> 2);
    const int nbase = n0 + wn * 32 + (lane & 3) * 2;
#pragma unroll
    for (int mf = 0; mf < 4; mf++)
#pragma unroll
        for (int nf = 0; nf < 4; nf++) {
            float* p0 = &out[(size_t)(mbase + mf * 16)     * N + nbase + nf * 8];
            float* p1 = &out[(size_t)(mbase + mf * 16 + 8) * N + nbase + nf * 8];
            *(float2*)p0 = make_float2(acc[mf][nf][0], acc[mf][nf][1]);
            *(float2*)p1 = make_float2(acc[mf][nf][2], acc[mf][nf][3]);
        }
}

// ----------------------------------------------------------------------------
extern "C" void kernel_launch(void* const* d_in, const int* in_sizes, int n_in,
                              void* d_out, int out_size) {
    (void)in_sizes; (void)n_in; (void)out_size;
    const float* x       = (const float*)d_in[0];
    const int*   qweight = (const int*)d_in[1];
    const float* scales  = (const float*)d_in[2];
    const int*   qzeros  = (const int*)d_in[3];
    float* out = (float*)d_out;

    prep_kernel<<<(XWORK + WWORK + 255) / 256, 256>>>(x, qweight, scales, qzeros);

    cudaFuncSetAttribute(gemm_kernel, cudaFuncAttributeMaxDynamicSharedMemorySize,
                         SMEM_BYTES);
    dim3 grid(M / BM, N / BN);   // (64, 43), m-fast -> wave shares B via L2
    gemm_kernel<<<grid, THREADS, SMEM_BYTES>>>(out);
}